// round 16
// baseline (speedup 1.0000x reference)
#include <cuda_runtime.h>

// reblurWithKernel: spatially-varying 33x33 blur, per-4x4-block kernels.
// out[c,h,w] = sum_{u,v} in[clamp(h+u-16),clamp(w+v-16)] * K[u*33+v, h/4, w/4]
//
// R14 = R12 (32-wb x 1-hb tile, lane = wb -> 128B kernel LDG wavefronts;
// 12 warps = 3 channels x 4 u-quarters; cp.async patch prologue; u=32 slice
// front-loaded; kr software pipelining) plus:
//  (1) krB for the FIRST u-row is also preloaded before the prologue, and
//      krB(u+4) is prefetched after halfB(u): every kernel-row LDG in the
//      kernel now has a full compute shadow (R12 ate one ~600cyc DRAM stall
//      at the first loop head).
//  (2) the u=32 slice's tap-32 FMAs run only on q==3 warps (warp-uniform
//      branch); q<3 warps no longer multiply by a guaranteed zero.

#define KW     33
#define BLK    4
#define PAD    16
#define HH     512
#define WW     512
#define HB     128
#define WBNUM  128
#define KSTR   (HB*WBNUM)         // 16384 elements between taps
#define TWB    32                 // wb blocks per CTA
#define PROWS  36                 // 4 + 2*16
#define PCOLS  160                // 32*4 + 2*16
#define PSTR   164                // row stride (floats), 656B (16B aligned)
#define NTHREADS 384
#define SMEM_FLOATS (3 * PROWS * PSTR)
#define SMEM_BYTES  (SMEM_FLOATS * 4)
#define NUNITS (3 * PROWS * (PCOLS/4))   // 4320 float4 units

__global__ __launch_bounds__(NTHREADS, 2)
void reblur_kernel(const float* __restrict__ img,
                   const float* __restrict__ ker,
                   float* __restrict__ out)
{
    extern __shared__ __align__(16) float sm[];
    unsigned int sbase;
    asm("{ .reg .u64 t; cvta.to.shared.u64 t, %1; cvt.u32.u64 %0, t; }"
        : "=r"(sbase) : "l"(sm));

    const int tid = threadIdx.x;
    const int WB0 = blockIdx.x * TWB;
    const int HB0 = blockIdx.y;

    // ---- work mapping: 12 warps = 3 channels x 4 u-quarters ----
    const int w    = tid >> 5;
    const int lane = tid & 31;    // wb block within tile
    const int c    = w >> 2;      // 0..2 channel
    const int q    = w & 3;       // 0..3 u-quarter (u = q mod 4, u < 32)
    const int wb4  = lane * BLK;

    // kernel tap t element: ker[t*KSTR + hb*WBNUM + wb]; lanes = consecutive wb
    const float* kbase = ker + HB0 * WBNUM + (WB0 + lane);

    // ---- issue ALL first-wave kernel LDGs up front: krA(q), krB(q), krS ----
    float krA[17], krB[16], krS[8], k32s;
    {
        const float* kp = kbase + (q * KW) * KSTR;
#pragma unroll
        for (int v = 0; v < 17; v++)
            krA[v] = __ldg(kp + v * KSTR);
#pragma unroll
        for (int v = 0; v < 16; v++)
            krB[v] = __ldg(kp + (17 + v) * KSTR);
        const float* kps = kbase + (32 * KW + 8 * q) * KSTR;
#pragma unroll
        for (int i = 0; i < 8; i++)
            krS[i] = __ldg(kps + i * KSTR);
        k32s = (q == 3) ? __ldg(kbase + (32 * KW + 32) * KSTR) : 0.0f;
    }

    // ---- patch prologue: cp.async 16B for in-range units, scalar at edges ----
    const int row0 = HB0 * BLK - PAD;
    const int col0 = WB0 * BLK - PAD;
    for (int idx = tid; idx < NUNITS; idx += NTHREADS) {
        int cc0 = idx / (PROWS * 40);
        int rem = idx - cc0 * (PROWS * 40);
        int r   = rem / 40;
        int m   = rem - r * 40;
        int ir  = min(max(row0 + r, 0), HH - 1);
        int cs  = col0 + 4 * m;
        unsigned int dst = sbase + (unsigned)((cc0 * PROWS + r) * PSTR) * 4u
                         + (unsigned)m * 16u;
        if (cs >= 0 && cs + 4 <= WW) {
            const float* src = img + cc0 * (HH * WW) + ir * WW + cs;
            asm volatile("cp.async.cg.shared.global [%0], [%1], 16;"
                         :: "r"(dst), "l"(src));
        } else {
            const float* rowp = img + cc0 * (HH * WW) + ir * WW;
            float4 v;
            v.x = rowp[min(max(cs + 0, 0), WW - 1)];
            v.y = rowp[min(max(cs + 1, 0), WW - 1)];
            v.z = rowp[min(max(cs + 2, 0), WW - 1)];
            v.w = rowp[min(max(cs + 3, 0), WW - 1)];
            *reinterpret_cast<float4*>(
                sm + (cc0 * PROWS + r) * PSTR + 4 * m) = v;
        }
    }
    asm volatile("cp.async.commit_group;");
    asm volatile("cp.async.wait_group 0;" ::: "memory");
    __syncthreads();

    const float* spc = sm + c * (PROWS * PSTR);

    float acc[4][4];
#pragma unroll
    for (int i = 0; i < 4; i++)
#pragma unroll
        for (int j = 0; j < 4; j++)
            acc[i][j] = 0.0f;

    // ---- u=32 slice first: taps 8q..8q+7 (+ tap 32 for q==3 only) ----
#pragma unroll
    for (int oi = 0; oi < 4; oi++) {
        float rbS[12];   // cols (rel wb4) 8q .. 8q+11
        const float4* rp =
            reinterpret_cast<const float4*>(spc + (32 + oi) * PSTR + wb4 + 8 * q);
#pragma unroll
        for (int i = 0; i < 3; i++) {
            float4 t = rp[i];
            rbS[4*i+0] = t.x; rbS[4*i+1] = t.y;
            rbS[4*i+2] = t.z; rbS[4*i+3] = t.w;
        }
#pragma unroll
        for (int i = 0; i < 8; i++) {
            const float k = krS[i];
            acc[oi][0] += k * rbS[i + 0];
            acc[oi][1] += k * rbS[i + 1];
            acc[oi][2] += k * rbS[i + 2];
            acc[oi][3] += k * rbS[i + 3];
        }
        if (q == 3) {   // warp-uniform: only q==3 owns tap v=32
            acc[oi][0] += k32s * rbS[8];
            acc[oi][1] += k32s * rbS[9];
            acc[oi][2] += k32s * rbS[10];
            acc[oi][3] += k32s * rbS[11];
        }
    }

    // ---- main loop: u = q, q+4, ..., <32 (8 iterations) ----
#pragma unroll 1
    for (int u = q; u < 32; u += 4) {
        // halfA: taps 0..16, window cols 0..19
#pragma unroll
        for (int oi = 0; oi < 4; oi++) {
            float rb[20];
            const float4* rp =
                reinterpret_cast<const float4*>(spc + (u + oi) * PSTR + wb4);
#pragma unroll
            for (int i = 0; i < 5; i++) {
                float4 t = rp[i];
                rb[4*i+0] = t.x; rb[4*i+1] = t.y;
                rb[4*i+2] = t.z; rb[4*i+3] = t.w;
            }
#pragma unroll
            for (int v = 0; v < 17; v++) {
                const float k = krA[v];
                acc[oi][0] += k * rb[v + 0];
                acc[oi][1] += k * rb[v + 1];
                acc[oi][2] += k * rb[v + 2];
                acc[oi][3] += k * rb[v + 3];
            }
        }

        // prefetch krA(u+4) — consumed next iteration's halfA;
        // shadowed by this iteration's halfB compute
        if (u + 4 < 32) {
            const float* kp2 = kbase + ((u + 4) * KW) * KSTR;
#pragma unroll
            for (int v = 0; v < 17; v++)
                krA[v] = __ldg(kp2 + v * KSTR);
        }

        // halfB: taps 17..32, window cols 16..35 (rb2[k] = col 16+k)
#pragma unroll
        for (int oi = 0; oi < 4; oi++) {
            float rb2[20];
            const float4* rp =
                reinterpret_cast<const float4*>(spc + (u + oi) * PSTR + wb4 + 16);
#pragma unroll
            for (int i = 0; i < 5; i++) {
                float4 t = rp[i];
                rb2[4*i+0] = t.x; rb2[4*i+1] = t.y;
                rb2[4*i+2] = t.z; rb2[4*i+3] = t.w;
            }
#pragma unroll
            for (int v = 0; v < 16; v++) {
                const float k = krB[v];
                acc[oi][0] += k * rb2[v + 1];
                acc[oi][1] += k * rb2[v + 2];
                acc[oi][2] += k * rb2[v + 3];
                acc[oi][3] += k * rb2[v + 4];
            }
        }

        // prefetch krB(u+4) — consumed next iteration's halfB;
        // shadowed by next iteration's halfA compute + krA prefetch
        if (u + 4 < 32) {
            const float* kp2 = kbase + ((u + 4) * KW) * KSTR;
#pragma unroll
            for (int v = 0; v < 16; v++)
                krB[v] = __ldg(kp2 + (17 + v) * KSTR);
        }
    }

    // ---- combine the 4 u-quarters via smem (reuse patch buffer) ----
    __syncthreads();               // everyone done reading the patch
    const int unit = c * 32 + lane;        // 0..95
    if (q != 0) {
        float* dst = sm + ((q - 1) * 96 + unit) * 16;
#pragma unroll
        for (int oi = 0; oi < 4; oi++) {
            float4 v = make_float4(acc[oi][0], acc[oi][1], acc[oi][2], acc[oi][3]);
            *reinterpret_cast<float4*>(dst + oi * 4) = v;
        }
    }
    __syncthreads();
    if (q == 0) {
#pragma unroll
        for (int p = 0; p < 3; p++) {
            const float* src = sm + (p * 96 + unit) * 16;
#pragma unroll
            for (int oi = 0; oi < 4; oi++) {
                float4 o = *reinterpret_cast<const float4*>(src + oi * 4);
                acc[oi][0] += o.x; acc[oi][1] += o.y;
                acc[oi][2] += o.z; acc[oi][3] += o.w;
            }
        }
        // coalesced store: 32 lanes x 16B = 512B contiguous per row
        float* ob = out + c * (HH * WW) + (HB0 * BLK) * WW + (WB0 + lane) * BLK;
#pragma unroll
        for (int oi = 0; oi < 4; oi++) {
            float4 val = make_float4(acc[oi][0], acc[oi][1], acc[oi][2], acc[oi][3]);
            *reinterpret_cast<float4*>(ob + oi * WW) = val;
        }
    }
}

extern "C" void kernel_launch(void* const* d_in, const int* in_sizes, int n_in,
                              void* d_out, int out_size)
{
    const float* img = (const float*)d_in[0];  // (1,3,512,512) fp32
    const float* ker = (const float*)d_in[1];  // (1,1089,128,128) fp32
    float* out = (float*)d_out;                // (1,3,512,512) fp32
    (void)in_sizes; (void)n_in; (void)out_size;

    cudaFuncSetAttribute(reblur_kernel,
                         cudaFuncAttributeMaxDynamicSharedMemorySize, SMEM_BYTES);

    dim3 grid(WBNUM / TWB, HB);  // (4, 128) = 512 CTAs
    reblur_kernel<<<grid, NTHREADS, SMEM_BYTES>>>(img, ker, out);
}